// round 16
// baseline (speedup 1.0000x reference)
#include <cuda_runtime.h>

typedef unsigned long long u64;
typedef unsigned int u32;

#define NN 100000
#define NE 1600000
#define EMBD 128
#define G1D 512
#define G2D 64000
#define DD 64
#define ECD 16
#define NB 100
#define BKT 64

__device__ float g_h[NB * G1D];
__device__ float g_x[NN * DD];
__device__ float g_x2[NN * DD];
__device__ float g_y[NN * DD];
__device__ float g_agg[NN * DD];
__device__ int g_cnt[NN];
__device__ int g_srcb[(u64)NN * BKT];
__device__ float g_eab[(u64)NN * BKT * ECD];  // 410 MB bucket edge-attr
// A split into tf32 hi/lo, fragment-ordered: float4 index = (k8*7 + mt)*32 + lane
__device__ float g_ahi[64 * 7 * 32 * 4];
__device__ float g_alo[64 * 7 * 32 * 4];

namespace {
struct StreamInit {
    cudaStream_t s2;
    cudaEvent_t evA, evB;
    StreamInit() {
        cudaStreamCreate(&s2);
        cudaEventCreateWithFlags(&evA, cudaEventDisableTiming);
        cudaEventCreateWithFlags(&evB, cudaEventDisableTiming);
    }
};
StreamInit g_si;
}  // namespace

__device__ __forceinline__ u64 f2fma(u64 a, u64 b, u64 c) {
    u64 d;
    asm("fma.rn.f32x2 %0, %1, %2, %3;" : "=l"(d) : "l"(a), "l"(b), "l"(c));
    return d;
}
__device__ __forceinline__ u64 f2dup(float x) {
    u64 d;
    asm("mov.b64 %0, {%1, %2};" : "=l"(d) : "f"(x), "f"(x));
    return d;
}
__device__ __forceinline__ float2 f2unpack(u64 d) {
    float2 r;
    asm("mov.b64 {%0, %1}, %2;" : "=f"(r.x), "=f"(r.y) : "l"(d));
    return r;
}
__device__ __forceinline__ u32 tf32_of(float x) {
    u32 r;
    asm("cvt.rna.tf32.f32 %0, %1;" : "=r"(r) : "f"(x));
    return r;
}
__device__ __forceinline__ void mma_tf32(float* d, u32 a0, u32 a1, u32 a2, u32 a3,
                                         u32 b0, u32 b1) {
    asm volatile(
        "mma.sync.aligned.m16n8k8.row.col.f32.tf32.tf32.f32 "
        "{%0,%1,%2,%3}, {%4,%5,%6,%7}, {%8,%9}, {%0,%1,%2,%3};"
        : "+f"(d[0]), "+f"(d[1]), "+f"(d[2]), "+f"(d[3])
        : "r"(a0), "r"(a1), "r"(a2), "r"(a3), "r"(b0), "r"(b1));
}

__global__ __launch_bounds__(512) void k_mlp1(const float* __restrict__ emb,
                                              const float* __restrict__ W,
                                              const float* __restrict__ b) {
    __shared__ float sE[EMBD];
    int bid = blockIdx.x, tid = threadIdx.x;
    if (tid < EMBD) sE[tid] = emb[bid * EMBD + tid];
    __syncthreads();
    float acc = 0.f;
#pragma unroll 16
    for (int k = 0; k < EMBD; k++) acc += sE[k] * __ldg(&W[k * G1D + tid]);
    g_h[bid * G1D + tid] = fmaxf(acc + b[tid], 0.f);
}

// Split h into tf32 hi/lo in m16n8k8 A-fragment order.
__global__ __launch_bounds__(256) void k_aprep() {
    int t = blockIdx.x * 256 + threadIdx.x;
    if (t >= 64 * 7 * 32) return;
    int lane = t & 31;
    int mt = (t >> 5) % 7;
    int k8 = t / (32 * 7);
    int g = lane >> 2, th = lane & 3;
    int r0 = mt * 16 + g, r1 = r0 + 8;
    int c0 = k8 * 8 + th, c1 = c0 + 4;
    float v[4];
    v[0] = (r0 < NB) ? g_h[r0 * G1D + c0] : 0.f;
    v[1] = (r1 < NB) ? g_h[r1 * G1D + c0] : 0.f;
    v[2] = (r0 < NB) ? g_h[r0 * G1D + c1] : 0.f;
    v[3] = (r1 < NB) ? g_h[r1 * G1D + c1] : 0.f;
    float hi[4], lo[4];
#pragma unroll
    for (int j = 0; j < 4; j++) {
        u32 hb = tf32_of(v[j]);
        float hf = __uint_as_float(hb);
        hi[j] = hf;
        lo[j] = __uint_as_float(tf32_of(v[j] - hf));
    }
    float4* ph = reinterpret_cast<float4*>(g_ahi) + t;
    float4* pl = reinterpret_cast<float4*>(g_alo) + t;
    *ph = make_float4(hi[0], hi[1], hi[2], hi[3]);
    *pl = make_float4(lo[0], lo[1], lo[2], lo[3]);
}

// Tensor-core mlp2 (proven R10/R12 version).
__global__ __launch_bounds__(256) void k_mlp2t(const float* __restrict__ W,
                                               const float* __restrict__ bias) {
    __shared__ float sW[32][136];
    __shared__ float4 sAh[896];
    __shared__ float4 sAl[896];
    int tid = threadIdx.x;
    int warp = tid >> 5, lane = tid & 31;
    int n0 = blockIdx.x * 128;
    int g = lane >> 2, th = lane & 3;
    float acc[7][2][4];
#pragma unroll
    for (int mt = 0; mt < 7; mt++)
#pragma unroll
        for (int cn = 0; cn < 2; cn++)
#pragma unroll
            for (int j = 0; j < 4; j++) acc[mt][cn][j] = 0.f;

    int lr = tid >> 3;
    int lc = (tid & 7) * 16;

    for (int kc = 0; kc < 16; kc++) {
        const float* wg = W + (u64)(kc * 32 + lr) * G2D + n0 + lc;
        float4 t0 = __ldg(reinterpret_cast<const float4*>(wg) + 0);
        float4 t1 = __ldg(reinterpret_cast<const float4*>(wg) + 1);
        float4 t2 = __ldg(reinterpret_cast<const float4*>(wg) + 2);
        float4 t3 = __ldg(reinterpret_cast<const float4*>(wg) + 3);
        const float4* pah = reinterpret_cast<const float4*>(g_ahi) + kc * 896;
        const float4* pal = reinterpret_cast<const float4*>(g_alo) + kc * 896;
        float4 ah[4], al[4];
#pragma unroll
        for (int i = 0; i < 4; i++) {
            int idx = tid + i * 256;
            if (idx < 896) {
                ah[i] = __ldg(pah + idx);
                al[i] = __ldg(pal + idx);
            }
        }
        __syncthreads();
        *reinterpret_cast<float4*>(&sW[lr][lc + 0]) = t0;
        *reinterpret_cast<float4*>(&sW[lr][lc + 4]) = t1;
        *reinterpret_cast<float4*>(&sW[lr][lc + 8]) = t2;
        *reinterpret_cast<float4*>(&sW[lr][lc + 12]) = t3;
#pragma unroll
        for (int i = 0; i < 4; i++) {
            int idx = tid + i * 256;
            if (idx < 896) {
                sAh[idx] = ah[i];
                sAl[idx] = al[i];
            }
        }
        __syncthreads();
#pragma unroll
        for (int k8l = 0; k8l < 4; k8l++) {
            int kb = k8l * 8 + th;
            u32 bh[2][2], bl[2][2];
#pragma unroll
            for (int cn = 0; cn < 2; cn++) {
                int cb = warp * 16 + cn * 8 + g;
                float w0 = sW[kb][cb];
                float w1 = sW[kb + 4][cb];
                u32 h0 = tf32_of(w0);
                u32 h1 = tf32_of(w1);
                bh[cn][0] = h0;
                bh[cn][1] = h1;
                bl[cn][0] = tf32_of(w0 - __uint_as_float(h0));
                bl[cn][1] = tf32_of(w1 - __uint_as_float(h1));
            }
#pragma unroll
            for (int mt = 0; mt < 7; mt++) {
                float4 fah = sAh[(k8l * 7 + mt) * 32 + lane];
                float4 fal = sAl[(k8l * 7 + mt) * 32 + lane];
                u32 a0 = __float_as_uint(fah.x), a1 = __float_as_uint(fah.y);
                u32 a2 = __float_as_uint(fah.z), a3 = __float_as_uint(fah.w);
                u32 l0 = __float_as_uint(fal.x), l1 = __float_as_uint(fal.y);
                u32 l2 = __float_as_uint(fal.z), l3 = __float_as_uint(fal.w);
#pragma unroll
                for (int cn = 0; cn < 2; cn++) {
                    mma_tf32(acc[mt][cn], a0, a1, a2, a3, bh[cn][0], bh[cn][1]);
                    mma_tf32(acc[mt][cn], a0, a1, a2, a3, bl[cn][0], bl[cn][1]);
                    mma_tf32(acc[mt][cn], l0, l1, l2, l3, bh[cn][0], bh[cn][1]);
                }
            }
        }
    }
#pragma unroll
    for (int mt = 0; mt < 7; mt++) {
#pragma unroll
        for (int cn = 0; cn < 2; cn++) {
            int row0 = mt * 16 + g, row1 = row0 + 8;
            int col = n0 + warp * 16 + cn * 8 + 2 * th;
            float b0 = __ldg(&bias[col]);
            float b1 = __ldg(&bias[col + 1]);
            if (row0 < NB) {
                float2 st = make_float2(acc[mt][cn][0] + b0, acc[mt][cn][1] + b1);
                *reinterpret_cast<float2*>(&g_x[(u64)row0 * G2D + col]) = st;
            }
            if (row1 < NB) {
                float2 st = make_float2(acc[mt][cn][2] + b0, acc[mt][cn][3] + b1);
                *reinterpret_cast<float2*>(&g_x[(u64)row1 * G2D + col]) = st;
            }
        }
    }
}

__global__ void k_zero_cnt() {
    int i = blockIdx.x * 256 + threadIdx.x;
    if (i < NN) g_cnt[i] = 0;
}

// One-pass bucket scatter: replaces hist + scan1/2/3 + permgather.
// 4 lanes per edge: leader atomicAdd -> slot; full 64B record written in one
// wavefront; srcb written by leader.
__global__ __launch_bounds__(256) void k_bucket(const int* __restrict__ ei,
                                                const float* __restrict__ ea) {
    int tid = threadIdx.x;
    int t = tid & 3;
    int e = blockIdx.x * 64 + (tid >> 2);
    int lane = tid & 31;
    int dst = __ldg(&ei[NE + e]);
    int pos = 0;
    if (t == 0) pos = atomicAdd(&g_cnt[dst], 1);
    pos = __shfl_sync(0xffffffffu, pos, lane & ~3);
    u64 slot = (u64)dst * BKT + pos;
    if (t == 0) g_srcb[slot] = __ldg(&ei[e]);
    float4 v = __ldg(reinterpret_cast<const float4*>(ea) + (u64)e * 4 + t);
    reinterpret_cast<float4*>(g_eab)[slot * 4 + t] = v;
}

__global__ __launch_bounds__(128) void k_ynode(const float* __restrict__ x,
                                               const float* __restrict__ mW,
                                               const float* __restrict__ mb) {
    __shared__ float sX[64][65];
    __shared__ float sW[64][64];
    int tid = threadIdx.x;
    int node0 = blockIdx.x * 64;
    for (int i = tid; i < 64 * 64; i += 128) sW[i >> 6][i & 63] = mW[i];
    for (int i = tid; i < 64 * 64; i += 128) {
        int n = i >> 6, c = i & 63;
        int nn = node0 + n;
        if (nn >= NN) nn = NN - 1;
        sX[n][c] = x[(u64)nn * DD + c];
    }
    __syncthreads();
    int f0 = (tid & 7) * 8;
    int n0 = (tid >> 3) * 4;
    u64 acc[4][4];
#pragma unroll
    for (int j = 0; j < 4; j++)
#pragma unroll
        for (int c = 0; c < 4; c++) acc[j][c] = 0ull;
#pragma unroll 8
    for (int k = 0; k < 64; k++) {
        ulonglong2 w01 = *reinterpret_cast<const ulonglong2*>(&sW[k][f0]);
        ulonglong2 w23 = *reinterpret_cast<const ulonglong2*>(&sW[k][f0 + 4]);
#pragma unroll
        for (int j = 0; j < 4; j++) {
            u64 a = f2dup(sX[n0 + j][k]);
            acc[j][0] = f2fma(a, w01.x, acc[j][0]);
            acc[j][1] = f2fma(a, w01.y, acc[j][1]);
            acc[j][2] = f2fma(a, w23.x, acc[j][2]);
            acc[j][3] = f2fma(a, w23.y, acc[j][3]);
        }
    }
    float2 bv[4];
#pragma unroll
    for (int c = 0; c < 4; c++)
        bv[c] = *reinterpret_cast<const float2*>(mb + f0 + 2 * c);
#pragma unroll
    for (int j = 0; j < 4; j++) {
        int nn = node0 + n0 + j;
        if (nn < NN) {
            float o[8];
#pragma unroll
            for (int c = 0; c < 4; c++) {
                float2 v = f2unpack(acc[j][c]);
                o[2 * c] = v.x + bv[c].x;
                o[2 * c + 1] = v.y + bv[c].y;
            }
            float* yp = g_y + (u64)nn * DD + f0;
            *reinterpret_cast<float4*>(yp) = make_float4(o[0], o[1], o[2], o[3]);
            *reinterpret_cast<float4*>(yp + 4) = make_float4(o[4], o[5], o[6], o[7]);
        }
    }
}

// k_agg: bucket-addressed, scalar FFMA, 2-edge unroll.
#define EDGE_SCALAR(ar, yv)                                                     \
    {                                                                           \
        float zx0 = 0.f, zx1 = 0.f, zy0 = 0.f, zy1 = 0.f;                       \
        _Pragma("unroll") for (int k = 0; k < 16; k += 2) {                     \
            zx0 = fmaf(ar[k], wx[k], zx0);                                      \
            zy0 = fmaf(ar[k], wy[k], zy0);                                      \
            zx1 = fmaf(ar[k + 1], wx[k + 1], zx1);                              \
            zy1 = fmaf(ar[k + 1], wy[k + 1], zy1);                              \
        }                                                                       \
        accx += fmaxf(yv.x + (zx0 + zx1), 0.f);                                 \
        accy += fmaxf(yv.y + (zy0 + zy1), 0.f);                                 \
    }

__global__ __launch_bounds__(256) void k_agg(const float* __restrict__ mW) {
    __shared__ float sWe[16][64];
    int tid = threadIdx.x;
    for (int i = tid; i < 16 * 64; i += 256) sWe[i >> 6][i & 63] = mW[64 * DD + i];
    __syncthreads();
    int lane = tid & 31;
    int node = blockIdx.x * 8 + (tid >> 5);
    float wx[16], wy[16];
#pragma unroll
    for (int k = 0; k < 16; k++) {
        wx[k] = sWe[k][2 * lane];
        wy[k] = sWe[k][2 * lane + 1];
    }
    int c = g_cnt[node];
    if (c > BKT) c = BKT;
    u64 base = (u64)node * BKT;
    float accx = 0.f, accy = 0.f;
    int i = 0;
    for (; i + 2 <= c; i += 2) {
        int s0 = __ldg(&g_srcb[base + i]);
        int s1 = __ldg(&g_srcb[base + i + 1]);
        const float4* p = reinterpret_cast<const float4*>(g_eab + (base + i) * ECD);
        float4 a0 = __ldg(p + 0), a1 = __ldg(p + 1), a2 = __ldg(p + 2), a3 = __ldg(p + 3);
        float4 c0 = __ldg(p + 4), c1 = __ldg(p + 5), c2 = __ldg(p + 6), c3 = __ldg(p + 7);
        float2 y0 = __ldg(reinterpret_cast<const float2*>(g_y + (u64)s0 * DD) + lane);
        float2 y1 = __ldg(reinterpret_cast<const float2*>(g_y + (u64)s1 * DD) + lane);
        float ar[16] = {a0.x, a0.y, a0.z, a0.w, a1.x, a1.y, a1.z, a1.w,
                        a2.x, a2.y, a2.z, a2.w, a3.x, a3.y, a3.z, a3.w};
        EDGE_SCALAR(ar, y0);
        float cr[16] = {c0.x, c0.y, c0.z, c0.w, c1.x, c1.y, c1.z, c1.w,
                        c2.x, c2.y, c2.z, c2.w, c3.x, c3.y, c3.z, c3.w};
        EDGE_SCALAR(cr, y1);
    }
    if (i < c) {
        int s0 = __ldg(&g_srcb[base + i]);
        const float4* p = reinterpret_cast<const float4*>(g_eab + (base + i) * ECD);
        float4 a0 = __ldg(p + 0), a1 = __ldg(p + 1), a2 = __ldg(p + 2), a3 = __ldg(p + 3);
        float2 y0 = __ldg(reinterpret_cast<const float2*>(g_y + (u64)s0 * DD) + lane);
        float ar[16] = {a0.x, a0.y, a0.z, a0.w, a1.x, a1.y, a1.z, a1.w,
                        a2.x, a2.y, a2.z, a2.w, a3.x, a3.y, a3.z, a3.w};
        EDGE_SCALAR(ar, y0);
    }
    *reinterpret_cast<float2*>(g_agg + (u64)node * DD + 2 * lane) =
        make_float2(accx, accy);
}

#define UPD_SMEM (128 * 130 * 4 + 128 * 64 * 4)
__global__ __launch_bounds__(256) void k_update(const float* __restrict__ x,
                                                const float* __restrict__ uW,
                                                const float* __restrict__ ub,
                                                float* __restrict__ xo) {
    extern __shared__ float us[];
    float(*sIn)[130] = reinterpret_cast<float(*)[130]>(us);
    float(*sW)[64] = reinterpret_cast<float(*)[64]>(us + 128 * 130);
    int tid = threadIdx.x;
    int node0 = blockIdx.x * 128;
    for (int i = tid; i < 128 * 64; i += 256) sW[i >> 6][i & 63] = uW[i];
    for (int i = tid; i < 128 * 128; i += 256) {
        int n = i >> 7, c = i & 127;
        int nn = node0 + n;
        if (nn >= NN) nn = NN - 1;
        float v = (c < 64) ? x[(u64)nn * DD + c] : g_agg[(u64)nn * DD + c - 64];
        sIn[n][c] = v;
    }
    __syncthreads();
    int f0 = (tid & 7) * 8;
    int n0 = (tid >> 3) * 4;
    u64 acc[4][4];
#pragma unroll
    for (int j = 0; j < 4; j++)
#pragma unroll
        for (int c = 0; c < 4; c++) acc[j][c] = 0ull;
#pragma unroll 8
    for (int k = 0; k < 128; k++) {
        ulonglong2 w01 = *reinterpret_cast<const ulonglong2*>(&sW[k][f0]);
        ulonglong2 w23 = *reinterpret_cast<const ulonglong2*>(&sW[k][f0 + 4]);
#pragma unroll
        for (int j = 0; j < 4; j++) {
            u64 a = f2dup(sIn[n0 + j][k]);
            acc[j][0] = f2fma(a, w01.x, acc[j][0]);
            acc[j][1] = f2fma(a, w01.y, acc[j][1]);
            acc[j][2] = f2fma(a, w23.x, acc[j][2]);
            acc[j][3] = f2fma(a, w23.y, acc[j][3]);
        }
    }
    float2 bv[4];
#pragma unroll
    for (int c = 0; c < 4; c++)
        bv[c] = *reinterpret_cast<const float2*>(ub + f0 + 2 * c);
#pragma unroll
    for (int j = 0; j < 4; j++) {
        int nn = node0 + n0 + j;
        if (nn < NN) {
            float o[8];
#pragma unroll
            for (int c = 0; c < 4; c++) {
                float2 v = f2unpack(acc[j][c]);
                o[2 * c] = fmaxf(v.x + bv[c].x, 0.f);
                o[2 * c + 1] = fmaxf(v.y + bv[c].y, 0.f);
            }
            float* op = xo + (u64)nn * DD + f0;
            *reinterpret_cast<float4*>(op) = make_float4(o[0], o[1], o[2], o[3]);
            *reinterpret_cast<float4*>(op + 4) = make_float4(o[4], o[5], o[6], o[7]);
        }
    }
}

#define NM_SMEM (64 * 128 * 4 + 64 * 65 * 4 + 64 * 130 * 4 + 128 * 4 * 4)
__global__ __launch_bounds__(256) void k_nodemlp(const float* __restrict__ W1,
                                                 const float* __restrict__ b1,
                                                 const float* __restrict__ W2,
                                                 const float* __restrict__ b2,
                                                 float* __restrict__ out) {
    extern __shared__ float nsm[];
    float(*sW1)[128] = reinterpret_cast<float(*)[128]>(nsm);
    float(*sX)[65] = reinterpret_cast<float(*)[65]>(nsm + 64 * 128);
    float(*sH)[130] = reinterpret_cast<float(*)[130]>(nsm + 64 * 128 + 64 * 65);
    float(*sW2)[4] =
        reinterpret_cast<float(*)[4]>(nsm + 64 * 128 + 64 * 65 + 64 * 130);
    int tid = threadIdx.x;
    int node0 = blockIdx.x * 64;
    for (int i = tid; i < 64 * 128; i += 256) sW1[i >> 7][i & 127] = W1[i];
    if (tid < 128) {
        sW2[tid][0] = W2[tid * 3 + 0];
        sW2[tid][1] = W2[tid * 3 + 1];
        sW2[tid][2] = W2[tid * 3 + 2];
    }
    for (int i = tid; i < 64 * 64; i += 256) {
        int n = i >> 6, c = i & 63;
        int nn = node0 + n;
        if (nn >= NN) nn = NN - 1;
        sX[n][c] = g_x[(u64)nn * DD + c];
    }
    __syncthreads();
    int f0 = (tid & 15) * 8;
    int n0 = (tid >> 4) * 4;
    u64 acc[4][4];
#pragma unroll
    for (int j = 0; j < 4; j++)
#pragma unroll
        for (int c = 0; c < 4; c++) acc[j][c] = 0ull;
#pragma unroll 8
    for (int k = 0; k < 64; k++) {
        ulonglong2 w01 = *reinterpret_cast<const ulonglong2*>(&sW1[k][f0]);
        ulonglong2 w23 = *reinterpret_cast<const ulonglong2*>(&sW1[k][f0 + 4]);
#pragma unroll
        for (int j = 0; j < 4; j++) {
            u64 a = f2dup(sX[n0 + j][k]);
            acc[j][0] = f2fma(a, w01.x, acc[j][0]);
            acc[j][1] = f2fma(a, w01.y, acc[j][1]);
            acc[j][2] = f2fma(a, w23.x, acc[j][2]);
            acc[j][3] = f2fma(a, w23.y, acc[j][3]);
        }
    }
    float2 bv[4];
#pragma unroll
    for (int c = 0; c < 4; c++)
        bv[c] = *reinterpret_cast<const float2*>(b1 + f0 + 2 * c);
#pragma unroll
    for (int j = 0; j < 4; j++) {
#pragma unroll
        for (int c = 0; c < 4; c++) {
            float2 v = f2unpack(acc[j][c]);
            sH[n0 + j][f0 + 2 * c] = fmaxf(v.x + bv[c].x, 0.f);
            sH[n0 + j][f0 + 2 * c + 1] = fmaxf(v.y + bv[c].y, 0.f);
        }
    }
    __syncthreads();
    if (tid < 192) {
        int node = tid / 3, c = tid % 3;
        int nn = node0 + node;
        if (nn < NN) {
            float o = b2[c];
#pragma unroll 16
            for (int j = 0; j < 128; j++) o += sH[node][j] * sW2[j][c];
            out[(u64)nn * 3 + c] = o;
        }
    }
}

extern "C" void kernel_launch(void* const* d_in, const int* in_sizes, int n_in,
                              void* d_out, int out_size) {
    const float* emb = (const float*)d_in[0];
    const int* edge_index = (const int*)d_in[1];
    const float* edge_attr = (const float*)d_in[2];
    const float* Wg1 = (const float*)d_in[3];
    const float* bg1 = (const float*)d_in[4];
    const float* Wg2 = (const float*)d_in[5];
    const float* bg2 = (const float*)d_in[6];
    const float* mW0 = (const float*)d_in[7];
    const float* mb0 = (const float*)d_in[8];
    const float* uW0 = (const float*)d_in[9];
    const float* ub0 = (const float*)d_in[10];
    const float* mW1 = (const float*)d_in[11];
    const float* mb1 = (const float*)d_in[12];
    const float* uW1 = (const float*)d_in[13];
    const float* ub1 = (const float*)d_in[14];
    const float* nW1 = (const float*)d_in[15];
    const float* nb1 = (const float*)d_in[16];
    const float* nW2 = (const float*)d_in[17];
    const float* nb2 = (const float*)d_in[18];
    float* out = (float*)d_out;

    float *p_x, *p_x2;
    cudaGetSymbolAddress((void**)&p_x, g_x);
    cudaGetSymbolAddress((void**)&p_x2, g_x2);

    cudaFuncSetAttribute(k_update, cudaFuncAttributeMaxDynamicSharedMemorySize,
                         UPD_SMEM);
    cudaFuncSetAttribute(k_nodemlp, cudaFuncAttributeMaxDynamicSharedMemorySize,
                         NM_SMEM);

    // Fork: bucket prep on side stream, MLP chain on main stream.
    cudaEventRecord(g_si.evA, 0);
    cudaStreamWaitEvent(g_si.s2, g_si.evA, 0);
    k_zero_cnt<<<(NN + 255) / 256, 256, 0, g_si.s2>>>();   // launch 0
    // main-stream MLP chain
    k_mlp1<<<NB, 512>>>(emb, Wg1, bg1);                    // launch 1
    k_aprep<<<56, 256>>>();                                // launch 2
    // bucket pass (launch 3 -> profiled)
    k_bucket<<<NE / 64, 256, 0, g_si.s2>>>(edge_index, edge_attr);
    cudaEventRecord(g_si.evB, g_si.s2);
    k_mlp2t<<<G2D / 128, 256>>>(Wg2, bg2);                 // launch 4
    // main stream continues
    k_ynode<<<(NN + 63) / 64, 128>>>(p_x, mW0, mb0);
    cudaStreamWaitEvent(0, g_si.evB, 0);  // join before first k_agg
    k_agg<<<NN / 8, 256>>>(mW0);
    k_update<<<(NN + 127) / 128, 256, UPD_SMEM>>>(p_x, uW0, ub0, p_x2);
    k_ynode<<<(NN + 63) / 64, 128>>>(p_x2, mW1, mb1);
    k_agg<<<NN / 8, 256>>>(mW1);
    k_update<<<(NN + 127) / 128, 256, UPD_SMEM>>>(p_x2, uW1, ub1, p_x);
    k_nodemlp<<<(NN + 63) / 64, 256, NM_SMEM>>>(nW1, nb1, nW2, nb2, out);
}

// round 17
// speedup vs baseline: 1.5068x; 1.5068x over previous
#include <cuda_runtime.h>

typedef unsigned long long u64;
typedef unsigned int u32;

#define NN 100000
#define NE 1600000
#define EMBD 128
#define G1D 512
#define G2D 64000
#define DD 64
#define ECD 16
#define NB 100
#define NSCAN_BLKS 196

__device__ float g_h[NB * G1D];
__device__ float g_x[NN * DD];
__device__ float g_x2[NN * DD];
__device__ float g_y[NN * DD];
__device__ float g_agg[NN * DD];
__device__ int g_cnt[NN];
__device__ int g_rowptr[NN + 1];
__device__ int g_ofs[NN];
__device__ int g_bsum[NSCAN_BLKS];
__device__ int g_srcp[NE];
__device__ float g_eap[(u64)NE * ECD];
// A split into tf32 hi/lo, fragment-ordered: float4 index = (k8*7 + mt)*32 + lane
__device__ float g_ahi[64 * 7 * 32 * 4];
__device__ float g_alo[64 * 7 * 32 * 4];

namespace {
struct StreamInit {
    cudaStream_t s2;
    cudaEvent_t evA, evB;
    StreamInit() {
        cudaStreamCreate(&s2);
        cudaEventCreateWithFlags(&evA, cudaEventDisableTiming);
        cudaEventCreateWithFlags(&evB, cudaEventDisableTiming);
    }
};
StreamInit g_si;
}  // namespace

__device__ __forceinline__ u64 f2fma(u64 a, u64 b, u64 c) {
    u64 d;
    asm("fma.rn.f32x2 %0, %1, %2, %3;" : "=l"(d) : "l"(a), "l"(b), "l"(c));
    return d;
}
__device__ __forceinline__ u64 f2dup(float x) {
    u64 d;
    asm("mov.b64 %0, {%1, %2};" : "=l"(d) : "f"(x), "f"(x));
    return d;
}
__device__ __forceinline__ float2 f2unpack(u64 d) {
    float2 r;
    asm("mov.b64 {%0, %1}, %2;" : "=f"(r.x), "=f"(r.y) : "l"(d));
    return r;
}
__device__ __forceinline__ u32 tf32_of(float x) {
    u32 r;
    asm("cvt.rna.tf32.f32 %0, %1;" : "=r"(r) : "f"(x));
    return r;
}
__device__ __forceinline__ void mma_tf32(float* d, u32 a0, u32 a1, u32 a2, u32 a3,
                                         u32 b0, u32 b1) {
    asm volatile(
        "mma.sync.aligned.m16n8k8.row.col.f32.tf32.tf32.f32 "
        "{%0,%1,%2,%3}, {%4,%5,%6,%7}, {%8,%9}, {%0,%1,%2,%3};"
        : "+f"(d[0]), "+f"(d[1]), "+f"(d[2]), "+f"(d[3])
        : "r"(a0), "r"(a1), "r"(a2), "r"(a3), "r"(b0), "r"(b1));
}

__global__ __launch_bounds__(512) void k_mlp1(const float* __restrict__ emb,
                                              const float* __restrict__ W,
                                              const float* __restrict__ b) {
    __shared__ float sE[EMBD];
    int bid = blockIdx.x, tid = threadIdx.x;
    if (tid < EMBD) sE[tid] = emb[bid * EMBD + tid];
    __syncthreads();
    float acc = 0.f;
#pragma unroll 16
    for (int k = 0; k < EMBD; k++) acc += sE[k] * __ldg(&W[k * G1D + tid]);
    g_h[bid * G1D + tid] = fmaxf(acc + b[tid], 0.f);
}

// Split h into tf32 hi/lo in m16n8k8 A-fragment order.
__global__ __launch_bounds__(256) void k_aprep() {
    int t = blockIdx.x * 256 + threadIdx.x;
    if (t >= 64 * 7 * 32) return;
    int lane = t & 31;
    int mt = (t >> 5) % 7;
    int k8 = t / (32 * 7);
    int g = lane >> 2, th = lane & 3;
    int r0 = mt * 16 + g, r1 = r0 + 8;
    int c0 = k8 * 8 + th, c1 = c0 + 4;
    float v[4];
    v[0] = (r0 < NB) ? g_h[r0 * G1D + c0] : 0.f;
    v[1] = (r1 < NB) ? g_h[r1 * G1D + c0] : 0.f;
    v[2] = (r0 < NB) ? g_h[r0 * G1D + c1] : 0.f;
    v[3] = (r1 < NB) ? g_h[r1 * G1D + c1] : 0.f;
    float hi[4], lo[4];
#pragma unroll
    for (int j = 0; j < 4; j++) {
        u32 hb = tf32_of(v[j]);
        float hf = __uint_as_float(hb);
        hi[j] = hf;
        lo[j] = __uint_as_float(tf32_of(v[j] - hf));
    }
    float4* ph = reinterpret_cast<float4*>(g_ahi) + t;
    float4* pl = reinterpret_cast<float4*>(g_alo) + t;
    *ph = make_float4(hi[0], hi[1], hi[2], hi[3]);
    *pl = make_float4(lo[0], lo[1], lo[2], lo[3]);
}

// Tensor-core mlp2 (proven R10/R12 version).
__global__ __launch_bounds__(256) void k_mlp2t(const float* __restrict__ W,
                                               const float* __restrict__ bias) {
    __shared__ float sW[32][136];
    __shared__ float4 sAh[896];
    __shared__ float4 sAl[896];
    int tid = threadIdx.x;
    int warp = tid >> 5, lane = tid & 31;
    int n0 = blockIdx.x * 128;
    int g = lane >> 2, th = lane & 3;
    float acc[7][2][4];
#pragma unroll
    for (int mt = 0; mt < 7; mt++)
#pragma unroll
        for (int cn = 0; cn < 2; cn++)
#pragma unroll
            for (int j = 0; j < 4; j++) acc[mt][cn][j] = 0.f;

    int lr = tid >> 3;
    int lc = (tid & 7) * 16;

    for (int kc = 0; kc < 16; kc++) {
        const float* wg = W + (u64)(kc * 32 + lr) * G2D + n0 + lc;
        float4 t0 = __ldg(reinterpret_cast<const float4*>(wg) + 0);
        float4 t1 = __ldg(reinterpret_cast<const float4*>(wg) + 1);
        float4 t2 = __ldg(reinterpret_cast<const float4*>(wg) + 2);
        float4 t3 = __ldg(reinterpret_cast<const float4*>(wg) + 3);
        const float4* pah = reinterpret_cast<const float4*>(g_ahi) + kc * 896;
        const float4* pal = reinterpret_cast<const float4*>(g_alo) + kc * 896;
        float4 ah[4], al[4];
#pragma unroll
        for (int i = 0; i < 4; i++) {
            int idx = tid + i * 256;
            if (idx < 896) {
                ah[i] = __ldg(pah + idx);
                al[i] = __ldg(pal + idx);
            }
        }
        __syncthreads();
        *reinterpret_cast<float4*>(&sW[lr][lc + 0]) = t0;
        *reinterpret_cast<float4*>(&sW[lr][lc + 4]) = t1;
        *reinterpret_cast<float4*>(&sW[lr][lc + 8]) = t2;
        *reinterpret_cast<float4*>(&sW[lr][lc + 12]) = t3;
#pragma unroll
        for (int i = 0; i < 4; i++) {
            int idx = tid + i * 256;
            if (idx < 896) {
                sAh[idx] = ah[i];
                sAl[idx] = al[i];
            }
        }
        __syncthreads();
#pragma unroll
        for (int k8l = 0; k8l < 4; k8l++) {
            int kb = k8l * 8 + th;
            u32 bh[2][2], bl[2][2];
#pragma unroll
            for (int cn = 0; cn < 2; cn++) {
                int cb = warp * 16 + cn * 8 + g;
                float w0 = sW[kb][cb];
                float w1 = sW[kb + 4][cb];
                u32 h0 = tf32_of(w0);
                u32 h1 = tf32_of(w1);
                bh[cn][0] = h0;
                bh[cn][1] = h1;
                bl[cn][0] = tf32_of(w0 - __uint_as_float(h0));
                bl[cn][1] = tf32_of(w1 - __uint_as_float(h1));
            }
#pragma unroll
            for (int mt = 0; mt < 7; mt++) {
                float4 fah = sAh[(k8l * 7 + mt) * 32 + lane];
                float4 fal = sAl[(k8l * 7 + mt) * 32 + lane];
                u32 a0 = __float_as_uint(fah.x), a1 = __float_as_uint(fah.y);
                u32 a2 = __float_as_uint(fah.z), a3 = __float_as_uint(fah.w);
                u32 l0 = __float_as_uint(fal.x), l1 = __float_as_uint(fal.y);
                u32 l2 = __float_as_uint(fal.z), l3 = __float_as_uint(fal.w);
#pragma unroll
                for (int cn = 0; cn < 2; cn++) {
                    mma_tf32(acc[mt][cn], a0, a1, a2, a3, bh[cn][0], bh[cn][1]);
                    mma_tf32(acc[mt][cn], a0, a1, a2, a3, bl[cn][0], bl[cn][1]);
                    mma_tf32(acc[mt][cn], l0, l1, l2, l3, bh[cn][0], bh[cn][1]);
                }
            }
        }
    }
#pragma unroll
    for (int mt = 0; mt < 7; mt++) {
#pragma unroll
        for (int cn = 0; cn < 2; cn++) {
            int row0 = mt * 16 + g, row1 = row0 + 8;
            int col = n0 + warp * 16 + cn * 8 + 2 * th;
            float b0 = __ldg(&bias[col]);
            float b1 = __ldg(&bias[col + 1]);
            if (row0 < NB) {
                float2 st = make_float2(acc[mt][cn][0] + b0, acc[mt][cn][1] + b1);
                *reinterpret_cast<float2*>(&g_x[(u64)row0 * G2D + col]) = st;
            }
            if (row1 < NB) {
                float2 st = make_float2(acc[mt][cn][2] + b0, acc[mt][cn][3] + b1);
                *reinterpret_cast<float2*>(&g_x[(u64)row1 * G2D + col]) = st;
            }
        }
    }
}

__global__ void k_zero_cnt() {
    int i = blockIdx.x * 256 + threadIdx.x;
    if (i < NN) g_cnt[i] = 0;
}
__global__ void k_hist(const int* __restrict__ ei) {
    int e = blockIdx.x * 256 + threadIdx.x;
    if (e < NE) atomicAdd(&g_cnt[__ldg(&ei[NE + e])], 1);
}
__global__ __launch_bounds__(512) void k_scan1() {
    __shared__ int s[512];
    int i = blockIdx.x * 512 + threadIdx.x;
    int v = (i < NN) ? g_cnt[i] : 0;
    s[threadIdx.x] = v;
    __syncthreads();
#pragma unroll
    for (int off = 1; off < 512; off <<= 1) {
        int t = (threadIdx.x >= off) ? s[threadIdx.x - off] : 0;
        __syncthreads();
        s[threadIdx.x] += t;
        __syncthreads();
    }
    if (i < NN) g_rowptr[i] = s[threadIdx.x] - v;
    if (threadIdx.x == 511) g_bsum[blockIdx.x] = s[511];
}
__global__ __launch_bounds__(256) void k_scan2() {
    __shared__ int s[256];
    int tid = threadIdx.x;
    int v = (tid < NSCAN_BLKS) ? g_bsum[tid] : 0;
    s[tid] = v;
    __syncthreads();
#pragma unroll
    for (int off = 1; off < 256; off <<= 1) {
        int t = (tid >= off) ? s[tid - off] : 0;
        __syncthreads();
        s[tid] += t;
        __syncthreads();
    }
    if (tid < NSCAN_BLKS) g_bsum[tid] = s[tid] - v;
}
__global__ void k_scan3() {
    int i = blockIdx.x * 256 + threadIdx.x;
    if (i < NN) {
        int r = g_rowptr[i] + g_bsum[i >> 9];
        g_rowptr[i] = r;
        g_ofs[i] = r;
    }
    if (i == 0) g_rowptr[NN] = NE;
}

// permgather: 4 lanes cooperate per edge; full 64B record in one wavefront.
__global__ __launch_bounds__(256) void k_permgather(const int* __restrict__ ei,
                                                    const float* __restrict__ ea) {
    int tid = threadIdx.x;
    int t = tid & 3;
    int e = blockIdx.x * 64 + (tid >> 2);
    int lane = tid & 31;
    int dst = __ldg(&ei[NE + e]);
    int pos = 0;
    if (t == 0) pos = atomicAdd(&g_ofs[dst], 1);
    pos = __shfl_sync(0xffffffffu, pos, lane & ~3);
    if (t == 0) g_srcp[pos] = __ldg(&ei[e]);
    float4 v = __ldcs(reinterpret_cast<const float4*>(ea) + (u64)e * 4 + t);
    reinterpret_cast<float4*>(g_eap)[(u64)pos * 4 + t] = v;
}

__global__ __launch_bounds__(128) void k_ynode(const float* __restrict__ x,
                                               const float* __restrict__ mW,
                                               const float* __restrict__ mb) {
    __shared__ float sX[64][65];
    __shared__ float sW[64][64];
    int tid = threadIdx.x;
    int node0 = blockIdx.x * 64;
    for (int i = tid; i < 64 * 64; i += 128) sW[i >> 6][i & 63] = mW[i];
    for (int i = tid; i < 64 * 64; i += 128) {
        int n = i >> 6, c = i & 63;
        int nn = node0 + n;
        if (nn >= NN) nn = NN - 1;
        sX[n][c] = x[(u64)nn * DD + c];
    }
    __syncthreads();
    int f0 = (tid & 7) * 8;
    int n0 = (tid >> 3) * 4;
    u64 acc[4][4];
#pragma unroll
    for (int j = 0; j < 4; j++)
#pragma unroll
        for (int c = 0; c < 4; c++) acc[j][c] = 0ull;
#pragma unroll 8
    for (int k = 0; k < 64; k++) {
        ulonglong2 w01 = *reinterpret_cast<const ulonglong2*>(&sW[k][f0]);
        ulonglong2 w23 = *reinterpret_cast<const ulonglong2*>(&sW[k][f0 + 4]);
#pragma unroll
        for (int j = 0; j < 4; j++) {
            u64 a = f2dup(sX[n0 + j][k]);
            acc[j][0] = f2fma(a, w01.x, acc[j][0]);
            acc[j][1] = f2fma(a, w01.y, acc[j][1]);
            acc[j][2] = f2fma(a, w23.x, acc[j][2]);
            acc[j][3] = f2fma(a, w23.y, acc[j][3]);
        }
    }
    float2 bv[4];
#pragma unroll
    for (int c = 0; c < 4; c++)
        bv[c] = *reinterpret_cast<const float2*>(mb + f0 + 2 * c);
#pragma unroll
    for (int j = 0; j < 4; j++) {
        int nn = node0 + n0 + j;
        if (nn < NN) {
            float o[8];
#pragma unroll
            for (int c = 0; c < 4; c++) {
                float2 v = f2unpack(acc[j][c]);
                o[2 * c] = v.x + bv[c].x;
                o[2 * c + 1] = v.y + bv[c].y;
            }
            float* yp = g_y + (u64)nn * DD + f0;
            *reinterpret_cast<float4*>(yp) = make_float4(o[0], o[1], o[2], o[3]);
            *reinterpret_cast<float4*>(yp + 4) = make_float4(o[4], o[5], o[6], o[7]);
        }
    }
}

// k_agg: scalar FFMA, 2-edge unroll; streaming loads (__ldcs) for eap/srcp to
// protect g_y's L2 residency.
#define EDGE_SCALAR(ar, yv)                                                     \
    {                                                                           \
        float zx0 = 0.f, zx1 = 0.f, zy0 = 0.f, zy1 = 0.f;                       \
        _Pragma("unroll") for (int k = 0; k < 16; k += 2) {                     \
            zx0 = fmaf(ar[k], wx[k], zx0);                                      \
            zy0 = fmaf(ar[k], wy[k], zy0);                                      \
            zx1 = fmaf(ar[k + 1], wx[k + 1], zx1);                              \
            zy1 = fmaf(ar[k + 1], wy[k + 1], zy1);                              \
        }                                                                       \
        accx += fmaxf(yv.x + (zx0 + zx1), 0.f);                                 \
        accy += fmaxf(yv.y + (zy0 + zy1), 0.f);                                 \
    }

__global__ __launch_bounds__(256) void k_agg(const float* __restrict__ mW) {
    __shared__ float sWe[16][64];
    int tid = threadIdx.x;
    for (int i = tid; i < 16 * 64; i += 256) sWe[i >> 6][i & 63] = mW[64 * DD + i];
    __syncthreads();
    int lane = tid & 31;
    int node = blockIdx.x * 8 + (tid >> 5);
    float wx[16], wy[16];
#pragma unroll
    for (int k = 0; k < 16; k++) {
        wx[k] = sWe[k][2 * lane];
        wy[k] = sWe[k][2 * lane + 1];
    }
    int e = g_rowptr[node], e_end = g_rowptr[node + 1];
    float accx = 0.f, accy = 0.f;
    for (; e + 2 <= e_end; e += 2) {
        int s0 = __ldcs(&g_srcp[e]);
        int s1 = __ldcs(&g_srcp[e + 1]);
        const float4* p = reinterpret_cast<const float4*>(g_eap + (u64)e * ECD);
        float4 a0 = __ldcs(p + 0), a1 = __ldcs(p + 1), a2 = __ldcs(p + 2),
               a3 = __ldcs(p + 3);
        float4 c0 = __ldcs(p + 4), c1 = __ldcs(p + 5), c2 = __ldcs(p + 6),
               c3 = __ldcs(p + 7);
        float2 y0 = __ldg(reinterpret_cast<const float2*>(g_y + (u64)s0 * DD) + lane);
        float2 y1 = __ldg(reinterpret_cast<const float2*>(g_y + (u64)s1 * DD) + lane);
        float ar[16] = {a0.x, a0.y, a0.z, a0.w, a1.x, a1.y, a1.z, a1.w,
                        a2.x, a2.y, a2.z, a2.w, a3.x, a3.y, a3.z, a3.w};
        EDGE_SCALAR(ar, y0);
        float cr[16] = {c0.x, c0.y, c0.z, c0.w, c1.x, c1.y, c1.z, c1.w,
                        c2.x, c2.y, c2.z, c2.w, c3.x, c3.y, c3.z, c3.w};
        EDGE_SCALAR(cr, y1);
    }
    if (e < e_end) {
        int s0 = __ldcs(&g_srcp[e]);
        const float4* p = reinterpret_cast<const float4*>(g_eap + (u64)e * ECD);
        float4 a0 = __ldcs(p + 0), a1 = __ldcs(p + 1), a2 = __ldcs(p + 2),
               a3 = __ldcs(p + 3);
        float2 y0 = __ldg(reinterpret_cast<const float2*>(g_y + (u64)s0 * DD) + lane);
        float ar[16] = {a0.x, a0.y, a0.z, a0.w, a1.x, a1.y, a1.z, a1.w,
                        a2.x, a2.y, a2.z, a2.w, a3.x, a3.y, a3.z, a3.w};
        EDGE_SCALAR(ar, y0);
    }
    *reinterpret_cast<float2*>(g_agg + (u64)node * DD + 2 * lane) =
        make_float2(accx, accy);
}

#define UPD_SMEM (128 * 130 * 4 + 128 * 64 * 4)
__global__ __launch_bounds__(256) void k_update(const float* __restrict__ x,
                                                const float* __restrict__ uW,
                                                const float* __restrict__ ub,
                                                float* __restrict__ xo) {
    extern __shared__ float us[];
    float(*sIn)[130] = reinterpret_cast<float(*)[130]>(us);
    float(*sW)[64] = reinterpret_cast<float(*)[64]>(us + 128 * 130);
    int tid = threadIdx.x;
    int node0 = blockIdx.x * 128;
    for (int i = tid; i < 128 * 64; i += 256) sW[i >> 6][i & 63] = uW[i];
    for (int i = tid; i < 128 * 128; i += 256) {
        int n = i >> 7, c = i & 127;
        int nn = node0 + n;
        if (nn >= NN) nn = NN - 1;
        float v = (c < 64) ? x[(u64)nn * DD + c] : g_agg[(u64)nn * DD + c - 64];
        sIn[n][c] = v;
    }
    __syncthreads();
    int f0 = (tid & 7) * 8;
    int n0 = (tid >> 3) * 4;
    u64 acc[4][4];
#pragma unroll
    for (int j = 0; j < 4; j++)
#pragma unroll
        for (int c = 0; c < 4; c++) acc[j][c] = 0ull;
#pragma unroll 8
    for (int k = 0; k < 128; k++) {
        ulonglong2 w01 = *reinterpret_cast<const ulonglong2*>(&sW[k][f0]);
        ulonglong2 w23 = *reinterpret_cast<const ulonglong2*>(&sW[k][f0 + 4]);
#pragma unroll
        for (int j = 0; j < 4; j++) {
            u64 a = f2dup(sIn[n0 + j][k]);
            acc[j][0] = f2fma(a, w01.x, acc[j][0]);
            acc[j][1] = f2fma(a, w01.y, acc[j][1]);
            acc[j][2] = f2fma(a, w23.x, acc[j][2]);
            acc[j][3] = f2fma(a, w23.y, acc[j][3]);
        }
    }
    float2 bv[4];
#pragma unroll
    for (int c = 0; c < 4; c++)
        bv[c] = *reinterpret_cast<const float2*>(ub + f0 + 2 * c);
#pragma unroll
    for (int j = 0; j < 4; j++) {
        int nn = node0 + n0 + j;
        if (nn < NN) {
            float o[8];
#pragma unroll
            for (int c = 0; c < 4; c++) {
                float2 v = f2unpack(acc[j][c]);
                o[2 * c] = fmaxf(v.x + bv[c].x, 0.f);
                o[2 * c + 1] = fmaxf(v.y + bv[c].y, 0.f);
            }
            float* op = xo + (u64)nn * DD + f0;
            *reinterpret_cast<float4*>(op) = make_float4(o[0], o[1], o[2], o[3]);
            *reinterpret_cast<float4*>(op + 4) = make_float4(o[4], o[5], o[6], o[7]);
        }
    }
}

#define NM_SMEM (64 * 128 * 4 + 64 * 65 * 4 + 64 * 130 * 4 + 128 * 4 * 4)
__global__ __launch_bounds__(256) void k_nodemlp(const float* __restrict__ W1,
                                                 const float* __restrict__ b1,
                                                 const float* __restrict__ W2,
                                                 const float* __restrict__ b2,
                                                 float* __restrict__ out) {
    extern __shared__ float nsm[];
    float(*sW1)[128] = reinterpret_cast<float(*)[128]>(nsm);
    float(*sX)[65] = reinterpret_cast<float(*)[65]>(nsm + 64 * 128);
    float(*sH)[130] = reinterpret_cast<float(*)[130]>(nsm + 64 * 128 + 64 * 65);
    float(*sW2)[4] =
        reinterpret_cast<float(*)[4]>(nsm + 64 * 128 + 64 * 65 + 64 * 130);
    int tid = threadIdx.x;
    int node0 = blockIdx.x * 64;
    for (int i = tid; i < 64 * 128; i += 256) sW1[i >> 7][i & 127] = W1[i];
    if (tid < 128) {
        sW2[tid][0] = W2[tid * 3 + 0];
        sW2[tid][1] = W2[tid * 3 + 1];
        sW2[tid][2] = W2[tid * 3 + 2];
    }
    for (int i = tid; i < 64 * 64; i += 256) {
        int n = i >> 6, c = i & 63;
        int nn = node0 + n;
        if (nn >= NN) nn = NN - 1;
        sX[n][c] = g_x[(u64)nn * DD + c];
    }
    __syncthreads();
    int f0 = (tid & 15) * 8;
    int n0 = (tid >> 4) * 4;
    u64 acc[4][4];
#pragma unroll
    for (int j = 0; j < 4; j++)
#pragma unroll
        for (int c = 0; c < 4; c++) acc[j][c] = 0ull;
#pragma unroll 8
    for (int k = 0; k < 64; k++) {
        ulonglong2 w01 = *reinterpret_cast<const ulonglong2*>(&sW1[k][f0]);
        ulonglong2 w23 = *reinterpret_cast<const ulonglong2*>(&sW1[k][f0 + 4]);
#pragma unroll
        for (int j = 0; j < 4; j++) {
            u64 a = f2dup(sX[n0 + j][k]);
            acc[j][0] = f2fma(a, w01.x, acc[j][0]);
            acc[j][1] = f2fma(a, w01.y, acc[j][1]);
            acc[j][2] = f2fma(a, w23.x, acc[j][2]);
            acc[j][3] = f2fma(a, w23.y, acc[j][3]);
        }
    }
    float2 bv[4];
#pragma unroll
    for (int c = 0; c < 4; c++)
        bv[c] = *reinterpret_cast<const float2*>(b1 + f0 + 2 * c);
#pragma unroll
    for (int j = 0; j < 4; j++) {
#pragma unroll
        for (int c = 0; c < 4; c++) {
            float2 v = f2unpack(acc[j][c]);
            sH[n0 + j][f0 + 2 * c] = fmaxf(v.x + bv[c].x, 0.f);
            sH[n0 + j][f0 + 2 * c + 1] = fmaxf(v.y + bv[c].y, 0.f);
        }
    }
    __syncthreads();
    if (tid < 192) {
        int node = tid / 3, c = tid % 3;
        int nn = node0 + node;
        if (nn < NN) {
            float o = b2[c];
#pragma unroll 16
            for (int j = 0; j < 128; j++) o += sH[node][j] * sW2[j][c];
            out[(u64)nn * 3 + c] = o;
        }
    }
}

extern "C" void kernel_launch(void* const* d_in, const int* in_sizes, int n_in,
                              void* d_out, int out_size) {
    const float* emb = (const float*)d_in[0];
    const int* edge_index = (const int*)d_in[1];
    const float* edge_attr = (const float*)d_in[2];
    const float* Wg1 = (const float*)d_in[3];
    const float* bg1 = (const float*)d_in[4];
    const float* Wg2 = (const float*)d_in[5];
    const float* bg2 = (const float*)d_in[6];
    const float* mW0 = (const float*)d_in[7];
    const float* mb0 = (const float*)d_in[8];
    const float* uW0 = (const float*)d_in[9];
    const float* ub0 = (const float*)d_in[10];
    const float* mW1 = (const float*)d_in[11];
    const float* mb1 = (const float*)d_in[12];
    const float* uW1 = (const float*)d_in[13];
    const float* ub1 = (const float*)d_in[14];
    const float* nW1 = (const float*)d_in[15];
    const float* nb1 = (const float*)d_in[16];
    const float* nW2 = (const float*)d_in[17];
    const float* nb2 = (const float*)d_in[18];
    float* out = (float*)d_out;

    float *p_x, *p_x2;
    cudaGetSymbolAddress((void**)&p_x, g_x);
    cudaGetSymbolAddress((void**)&p_x2, g_x2);

    cudaFuncSetAttribute(k_update, cudaFuncAttributeMaxDynamicSharedMemorySize,
                         UPD_SMEM);
    cudaFuncSetAttribute(k_nodemlp, cudaFuncAttributeMaxDynamicSharedMemorySize,
                         NM_SMEM);

    // Fork: CSR prep chain on side stream, MLP chain on main stream.
    cudaEventRecord(g_si.evA, 0);
    cudaStreamWaitEvent(g_si.s2, g_si.evA, 0);
    k_zero_cnt<<<(NN + 255) / 256, 256, 0, g_si.s2>>>();
    // main-stream MLP chain (mlp2t at launch index 3)
    k_mlp1<<<NB, 512>>>(emb, Wg1, bg1);
    k_aprep<<<56, 256>>>();
    k_mlp2t<<<G2D / 128, 256>>>(Wg2, bg2);
    // side-stream prep chain
    k_hist<<<(NE + 255) / 256, 256, 0, g_si.s2>>>(edge_index);
    k_scan1<<<NSCAN_BLKS, 512, 0, g_si.s2>>>();
    k_scan2<<<1, 256, 0, g_si.s2>>>();
    k_scan3<<<(NN + 255) / 256, 256, 0, g_si.s2>>>();
    k_permgather<<<NE / 64, 256, 0, g_si.s2>>>(edge_index, edge_attr);
    cudaEventRecord(g_si.evB, g_si.s2);
    // main stream continues
    k_ynode<<<(NN + 63) / 64, 128>>>(p_x, mW0, mb0);
    cudaStreamWaitEvent(0, g_si.evB, 0);  // join before first k_agg
    k_agg<<<NN / 8, 256>>>(mW0);
    k_update<<<(NN + 127) / 128, 256, UPD_SMEM>>>(p_x, uW0, ub0, p_x2);
    k_ynode<<<(NN + 63) / 64, 128>>>(p_x2, mW1, mb1);
    k_agg<<<NN / 8, 256>>>(mW1);
    k_update<<<(NN + 127) / 128, 256, UPD_SMEM>>>(p_x2, uW1, ub1, p_x);
    k_nodemlp<<<(NN + 63) / 64, 256, NM_SMEM>>>(nW1, nb1, nW2, nb2, out);
}